// round 5
// baseline (speedup 1.0000x reference)
#include <cuda_runtime.h>
#include <math.h>

#define T_  200
#define N_  256
#define H_  128
#define H4_ 512
#define V_  50000

// ---------------- scratch (device globals; no runtime allocation) ----------
__device__ float g_xw[(size_t)T_ * N_ * H4_];   // [t][n][4H]  ~105 MB
__device__ float g_h [(size_t)T_ * N_ * H_];    // [t][n][H]   ~26 MB
__device__ float g_c [(size_t)T_ * N_ * H_];
__device__ float g_hsum[N_ * H_];
__device__ float g_csum[N_ * H_];
__device__ float g_hmean[N_ * H_];

// ---------------- kernel 1: xw[t,n,:] = emb[seq[t,n]] @ W + b ---------------
// rows = T*N = 51200, cols = 4H = 512, K = H = 128.
// Tile 64 rows x 64 cols, 256 threads, 4x4 register blocking, full-K smem.
#define XW_AS_LD 132   // padded row stride for A tile (bank-conflict free)
#define XW_SMEM_BYTES ((64 * XW_AS_LD + 128 * 64) * 4)

__global__ __launch_bounds__(256) void xw_kernel(
    const int* __restrict__ seq, const float* __restrict__ emb,
    const float* __restrict__ W, const float* __restrict__ b)
{
    extern __shared__ float dynsmem[];
    float* As = dynsmem;                  // [64][XW_AS_LD], uses first 128 cols
    float* Bs = dynsmem + 64 * XW_AS_LD;  // [128][64]

    const int r0 = blockIdx.x * 64;
    const int j0 = blockIdx.y * 64;
    const int tid = threadIdx.x;

    // Load A tile (gathered embedding rows): row = tid/4, 32 floats each.
    {
        const int row = tid >> 2, part = tid & 3;
        const int s = seq[r0 + row];
        const float4* src = (const float4*)(emb + (size_t)s * H_ + part * 32);
        float4* dst = (float4*)(As + row * XW_AS_LD + part * 32);
        #pragma unroll
        for (int i = 0; i < 8; i++) dst[i] = src[i];
    }
    // Load B tile: W[k][j0..j0+63]
    {
        const int k = tid >> 1, part = tid & 1;
        const float4* src = (const float4*)(W + (size_t)k * H4_ + j0 + part * 32);
        float4* dst = (float4*)(Bs + k * 64 + part * 32);
        #pragma unroll
        for (int i = 0; i < 8; i++) dst[i] = src[i];
    }
    __syncthreads();

    const int tx = tid & 15;   // col group (4 cols)
    const int ty = tid >> 4;   // row group (4 rows)
    float acc[4][4] = {};

    #pragma unroll 4
    for (int k = 0; k < 128; k++) {
        float a0 = As[(ty * 4 + 0) * XW_AS_LD + k];
        float a1 = As[(ty * 4 + 1) * XW_AS_LD + k];
        float a2 = As[(ty * 4 + 2) * XW_AS_LD + k];
        float a3 = As[(ty * 4 + 3) * XW_AS_LD + k];
        float4 b4 = *(const float4*)(Bs + k * 64 + tx * 4);
        acc[0][0] += a0 * b4.x; acc[0][1] += a0 * b4.y; acc[0][2] += a0 * b4.z; acc[0][3] += a0 * b4.w;
        acc[1][0] += a1 * b4.x; acc[1][1] += a1 * b4.y; acc[1][2] += a1 * b4.z; acc[1][3] += a1 * b4.w;
        acc[2][0] += a2 * b4.x; acc[2][1] += a2 * b4.y; acc[2][2] += a2 * b4.z; acc[2][3] += a2 * b4.w;
        acc[3][0] += a3 * b4.x; acc[3][1] += a3 * b4.y; acc[3][2] += a3 * b4.z; acc[3][3] += a3 * b4.w;
    }

    #pragma unroll
    for (int i = 0; i < 4; i++) {
        const size_t r = r0 + ty * 4 + i;
        #pragma unroll
        for (int jj = 0; jj < 4; jj++) {
            const int j = j0 + tx * 4 + jj;
            g_xw[r * H4_ + j] = acc[i][jj] + b[j];
        }
    }
}

// ---------------- kernel 2: per-step aggregation ----------------------------
// h_sum[n,h] = sum_{t'<t} topo[t,n,t'] * h_store[t',n,h]   (same for c)
__global__ __launch_bounds__(128) void agg_kernel(const float* __restrict__ topo, int t)
{
    const int n = blockIdx.x;
    const int h = threadIdx.x;   // 128

    __shared__ float s_topo[T_];
    const float* trow = topo + ((size_t)t * N_ + n) * T_;
    for (int i = h; i < t; i += 128) s_topo[i] = trow[i];
    __syncthreads();

    float hs = 0.f, cs = 0.f;
    const float* hp = g_h + n * H_ + h;
    const float* cp = g_c + n * H_ + h;
    #pragma unroll 4
    for (int tp = 0; tp < t; tp++) {
        const float w = s_topo[tp];
        hs += w * hp[(size_t)tp * N_ * H_];
        cs += w * cp[(size_t)tp * N_ * H_];
    }
    g_hsum[n * H_ + h] = hs;
    g_csum[n * H_ + h] = cs;
}

// ---------------- kernel 3: gates GEMM + LSTM cell (fused) ------------------
// gates[n, g*128+h] = hsum[n,:] @ U[:, g*128+h] + xw[t,n,g*128+h]
// Tile: 16 n x 16 h-outputs (x 4 gates), 256 threads, one (n,h) pair each.
#define GS_HS_LD 129
__global__ __launch_bounds__(256) void gates_kernel(
    const float* __restrict__ U, const float* __restrict__ smask, int t)
{
    __shared__ float s_hs[16 * GS_HS_LD];   // [nn][k]
    __shared__ float s_U[128 * 64];         // [k][hh*4 + gate]

    const int n0 = blockIdx.x * 16;
    const int h0 = blockIdx.y * 16;
    const int tid = threadIdx.x;

    for (int idx = tid; idx < 16 * 128; idx += 256) {
        const int nn = idx >> 7, k = idx & 127;
        s_hs[nn * GS_HS_LD + k] = g_hsum[(n0 + nn) * H_ + k];
    }
    for (int idx = tid; idx < 128 * 64; idx += 256) {
        const int k  = idx >> 6;
        const int g  = (idx >> 4) & 3;
        const int hh = idx & 15;
        s_U[k * 64 + hh * 4 + g] = U[(size_t)k * H4_ + g * H_ + h0 + hh];
    }
    __syncthreads();

    const int hh = tid & 15;
    const int nn = tid >> 4;
    const int n = n0 + nn;
    const int h = h0 + hh;

    const float* xw = g_xw + ((size_t)t * N_ + n) * H4_;
    float ai = xw[0 * H_ + h];
    float af = xw[1 * H_ + h];
    float ao = xw[2 * H_ + h];
    float ag = xw[3 * H_ + h];

    #pragma unroll 4
    for (int k = 0; k < 128; k++) {
        const float a = s_hs[nn * GS_HS_LD + k];
        const float4 u4 = *(const float4*)(s_U + k * 64 + hh * 4);
        ai += a * u4.x; af += a * u4.y; ao += a * u4.z; ag += a * u4.w;
    }

    const float i_ = 1.f / (1.f + expf(-ai));
    const float f_ = 1.f / (1.f + expf(-af));
    const float o_ = 1.f / (1.f + expf(-ao));
    const float g_ = tanhf(ag);
    const float csum = g_csum[n * H_ + h];
    const float m = smask[t * N_ + n];

    const float c = m * (f_ * csum + i_ * g_);
    const float hv = m * (o_ * tanhf(c));

    g_c[((size_t)t * N_ + n) * H_ + h] = c;
    g_h[((size_t)t * N_ + n) * H_ + h] = hv;
}

// ---------------- kernel 4: masked mean over time ---------------------------
__global__ __launch_bounds__(128) void hmean_kernel(const float* __restrict__ smask)
{
    const int n = blockIdx.x;
    const int h = threadIdx.x;
    float acc = 0.f, len = 0.f;
    for (int t = 0; t < T_; t++) {
        const float m = smask[t * N_ + n];
        acc += m * g_h[((size_t)t * N_ + n) * H_ + h];
        len += m;
    }
    g_hmean[n * H_ + h] = acc / len;
}

// ---------------- kernel 5: out = hmean @ W_out + b_out ---------------------
// 256 x 50000, K=128. Tile 32 n x 128 v, 256 threads, 4x4 register blocking.
#define OUT_SMEM_BYTES ((32 * 128 + 128 * 128) * 4)
__global__ __launch_bounds__(256) void out_kernel(
    const float* __restrict__ Wo, const float* __restrict__ bo,
    float* __restrict__ out)
{
    extern __shared__ float dynsmem[];
    float* As = dynsmem;               // [32][128]
    float* Bs = dynsmem + 32 * 128;    // [128][128]

    const int v0 = blockIdx.x * 128;
    const int n0 = blockIdx.y * 32;
    const int tid = threadIdx.x;

    for (int idx = tid; idx < 32 * 128; idx += 256) {
        const int r = idx >> 7, k = idx & 127;
        As[r * 128 + k] = g_hmean[(n0 + r) * H_ + k];
    }
    for (int idx4 = tid; idx4 < 4096; idx4 += 256) {   // 128*128 floats as float4
        const int k = idx4 >> 5;
        const int c4 = idx4 & 31;
        const int v = v0 + c4 * 4;
        float4 val = make_float4(0.f, 0.f, 0.f, 0.f);
        if (v < V_) val = *(const float4*)(Wo + (size_t)k * V_ + v);
        *(float4*)(Bs + k * 128 + c4 * 4) = val;
    }
    __syncthreads();

    const int tx = tid & 31;   // 32 col groups of 4
    const int ty = tid >> 5;   // 8 row groups of 4
    float acc[4][4] = {};

    #pragma unroll 4
    for (int k = 0; k < 128; k++) {
        float a0 = As[(ty * 4 + 0) * 128 + k];
        float a1 = As[(ty * 4 + 1) * 128 + k];
        float a2 = As[(ty * 4 + 2) * 128 + k];
        float a3 = As[(ty * 4 + 3) * 128 + k];
        float4 b4 = *(const float4*)(Bs + k * 128 + tx * 4);
        acc[0][0] += a0 * b4.x; acc[0][1] += a0 * b4.y; acc[0][2] += a0 * b4.z; acc[0][3] += a0 * b4.w;
        acc[1][0] += a1 * b4.x; acc[1][1] += a1 * b4.y; acc[1][2] += a1 * b4.z; acc[1][3] += a1 * b4.w;
        acc[2][0] += a2 * b4.x; acc[2][1] += a2 * b4.y; acc[2][2] += a2 * b4.z; acc[2][3] += a2 * b4.w;
        acc[3][0] += a3 * b4.x; acc[3][1] += a3 * b4.y; acc[3][2] += a3 * b4.z; acc[3][3] += a3 * b4.w;
    }

    #pragma unroll
    for (int i = 0; i < 4; i++) {
        const size_t n = n0 + ty * 4 + i;
        #pragma unroll
        for (int jj = 0; jj < 4; jj++) {
            const int v = v0 + tx * 4 + jj;
            if (v < V_) out[n * V_ + v] = acc[i][jj] + bo[v];
        }
    }
}

// ---------------- launch ----------------------------------------------------
extern "C" void kernel_launch(void* const* d_in, const int* in_sizes, int n_in,
                              void* d_out, int out_size)
{
    const int*   seq   = (const int*)  d_in[0];   // (T,N) int32
    const float* smask = (const float*)d_in[1];   // (T,N)
    const float* topo  = (const float*)d_in[2];   // (T,N,T)
    const float* W     = (const float*)d_in[3];   // (H,4H)
    const float* U     = (const float*)d_in[4];   // (H,4H)
    const float* b     = (const float*)d_in[5];   // (4H,)
    const float* emb   = (const float*)d_in[6];   // (V,H)
    const float* Wo    = (const float*)d_in[7];   // (H,V)
    const float* bo    = (const float*)d_in[8];   // (V,)
    float* out = (float*)d_out;                   // (N,V)

    cudaFuncSetAttribute(xw_kernel,  cudaFuncAttributeMaxDynamicSharedMemorySize, XW_SMEM_BYTES);
    cudaFuncSetAttribute(out_kernel, cudaFuncAttributeMaxDynamicSharedMemorySize, OUT_SMEM_BYTES);

    // 1) parallel precompute of emb@W + b for all (t,n)
    xw_kernel<<<dim3((T_ * N_) / 64, H4_ / 64), 256, XW_SMEM_BYTES>>>(seq, emb, W, b);

    // 2) serial recurrence
    for (int t = 0; t < T_; t++) {
        agg_kernel<<<N_, H_>>>(topo, t);
        gates_kernel<<<dim3(N_ / 16, H_ / 16), 256>>>(U, smask, t);
    }

    // 3) masked mean + output projection
    hmean_kernel<<<N_, H_>>>(smask);
    out_kernel<<<dim3((V_ + 127) / 128, N_ / 32), 256, OUT_SMEM_BYTES>>>(Wo, bo, out);
}

// round 9
// speedup vs baseline: 1.8987x; 1.8987x over previous
#include <cuda_runtime.h>
#include <math.h>

#define T_  200
#define N_  256
#define H_  128
#define H4_ 512
#define V_  50000

#define NB   2            // batch elements per block
#define NBLK (N_ / NB)    // 128 persistent blocks

// ---------------- scratch (device globals; no runtime allocation) ----------
__device__ float g_xw[(size_t)T_ * N_ * H4_];              // [t][n][4H]  ~105 MB
// per-block-compact history: [block][t][h|c][nb][H]  (~52 MB, L2-resident)
__device__ float g_hist[(size_t)NBLK * T_ * 2 * NB * H_];
__device__ float g_hmean[N_ * H_];

// ---------------- kernel 1: xw[t,n,:] = emb[seq[t,n]] @ W + b ---------------
#define XW_AS_LD 132
#define XW_SMEM_BYTES ((64 * XW_AS_LD + 128 * 64) * 4)

__global__ __launch_bounds__(256) void xw_kernel(
    const int* __restrict__ seq, const float* __restrict__ emb,
    const float* __restrict__ W, const float* __restrict__ b)
{
    extern __shared__ float dynsmem[];
    float* As = dynsmem;                  // [64][XW_AS_LD]
    float* Bs = dynsmem + 64 * XW_AS_LD;  // [128][64]

    const int r0 = blockIdx.x * 64;
    const int j0 = blockIdx.y * 64;
    const int tid = threadIdx.x;

    {
        const int row = tid >> 2, part = tid & 3;
        const int s = seq[r0 + row];
        const float4* src = (const float4*)(emb + (size_t)s * H_ + part * 32);
        float4* dst = (float4*)(As + row * XW_AS_LD + part * 32);
        #pragma unroll
        for (int i = 0; i < 8; i++) dst[i] = src[i];
    }
    {
        const int k = tid >> 1, part = tid & 1;
        const float4* src = (const float4*)(W + (size_t)k * H4_ + j0 + part * 32);
        float4* dst = (float4*)(Bs + k * 64 + part * 32);
        #pragma unroll
        for (int i = 0; i < 8; i++) dst[i] = src[i];
    }
    __syncthreads();

    const int tx = tid & 15;
    const int ty = tid >> 4;
    float acc[4][4] = {};

    #pragma unroll 4
    for (int k = 0; k < 128; k++) {
        float a0 = As[(ty * 4 + 0) * XW_AS_LD + k];
        float a1 = As[(ty * 4 + 1) * XW_AS_LD + k];
        float a2 = As[(ty * 4 + 2) * XW_AS_LD + k];
        float a3 = As[(ty * 4 + 3) * XW_AS_LD + k];
        float4 b4 = *(const float4*)(Bs + k * 64 + tx * 4);
        acc[0][0] += a0 * b4.x; acc[0][1] += a0 * b4.y; acc[0][2] += a0 * b4.z; acc[0][3] += a0 * b4.w;
        acc[1][0] += a1 * b4.x; acc[1][1] += a1 * b4.y; acc[1][2] += a1 * b4.z; acc[1][3] += a1 * b4.w;
        acc[2][0] += a2 * b4.x; acc[2][1] += a2 * b4.y; acc[2][2] += a2 * b4.z; acc[2][3] += a2 * b4.w;
        acc[3][0] += a3 * b4.x; acc[3][1] += a3 * b4.y; acc[3][2] += a3 * b4.z; acc[3][3] += a3 * b4.w;
    }

    #pragma unroll
    for (int i = 0; i < 4; i++) {
        const size_t r = r0 + ty * 4 + i;
        #pragma unroll
        for (int jj = 0; jj < 4; jj++) {
            const int j = j0 + tx * 4 + jj;
            g_xw[r * H4_ + j] = acc[i][jj] + b[j];
        }
    }
}

// ---------------- kernel 2: persistent recurrence ---------------------------
// One block per NB batch elements; runs all T_ steps internally.
// Thread j (of 256): owns U[:, j] in registers and streams U[:, 256+j] from smem.
// Agg/cell role: thread = (an = tid>>7, ak = tid&127) -> (n', h=k).
// smem: sU[128][256] (U cols 256..511) | s_hs[128][NB] | s_g[NB][512] | s_topo[NB][T_]
#define SM_SU   (128 * 256)
#define SM_HS   (128 * NB)
#define SM_G    (NB * H4_)
#define SM_TOPO (NB * T_)
#define REC_SMEM_BYTES ((SM_SU + SM_HS + SM_G + SM_TOPO) * 4)

__global__ __launch_bounds__(256, 1) void rec_kernel(
    const float* __restrict__ topo, const float* __restrict__ smask,
    const float* __restrict__ U)
{
    extern __shared__ float sm[];
    float* sU     = sm;                    // [k][j] j in [0,256) -> U col 256+j
    float* s_hs   = sU + SM_SU;            // [k][NB]
    float* s_g    = s_hs + SM_HS;          // [n'][512]
    float* s_topo = s_g + SM_G;            // [n'][T_]

    const int b   = blockIdx.x;
    const int tid = threadIdx.x;
    const int n0  = b * NB;
    const int an  = tid >> 7;     // n' in [0,NB)
    const int ak  = tid & 127;    // k / h index

    // ---- prologue: load U (half regs, half smem) ----
    float u[128];
    #pragma unroll
    for (int k = 0; k < 128; k++) u[k] = U[(size_t)k * H4_ + tid];
    for (int idx = tid; idx < 128 * 256; idx += 256) {
        const int k = idx >> 8, j = idx & 255;
        sU[idx] = U[(size_t)k * H4_ + 256 + j];
    }

    float* hist = g_hist + (size_t)b * T_ * 2 * NB * H_;   // [t][hc][n'][h]
    const int HSTRIDE = 2 * NB * H_;   // floats per t

    float hmean_acc = 0.f, len_acc = 0.f;
    __syncthreads();

    for (int t = 0; t < T_; t++) {
        // ---- stage topo rows (t' < t) ----
        #pragma unroll
        for (int nn = 0; nn < NB; nn++) {
            const float* trow = topo + ((size_t)t * N_ + n0 + nn) * T_;
            for (int i = tid; i < t; i += 256) s_topo[nn * T_ + i] = trow[i];
        }
        __syncthreads();   // sync A: topo ready; also guards s_hs reuse

        // ---- aggregation: hs/cs[n'=an, k=ak] over history ----
        float hs = 0.f, cs = 0.f;
        {
            const float* hp = hist + an * H_ + ak;          // h at [t'][0][an][ak]
            const float* tw = s_topo + an * T_;
            #pragma unroll 4
            for (int tp = 0; tp < t; tp++) {
                const float w = tw[tp];
                hs += w * hp[(size_t)tp * HSTRIDE];
                cs += w * hp[(size_t)tp * HSTRIDE + NB * H_];
            }
        }
        s_hs[ak * NB + an] = hs;
        __syncthreads();   // sync B: hs ready; also guards s_g/s_topo reuse

        // ---- gates GEMM: cols tid (regs) and 256+tid (smem), both n' ----
        {
            const float* xwp = g_xw + ((size_t)t * N_ + n0) * H4_;
            float a0 = xwp[tid];                 // n0, col tid
            float a1 = xwp[H4_ + tid];           // n1, col tid
            float a2 = xwp[256 + tid];           // n0, col 256+tid
            float a3 = xwp[H4_ + 256 + tid];     // n1, col 256+tid
            #pragma unroll
            for (int k = 0; k < 128; k++) {
                const float2 hv = *(const float2*)(s_hs + k * NB);
                const float ub = sU[k * 256 + tid];
                a0 += hv.x * u[k];
                a1 += hv.y * u[k];
                a2 += hv.x * ub;
                a3 += hv.y * ub;
            }
            s_g[0 * H4_ + tid]       = a0;
            s_g[1 * H4_ + tid]       = a1;
            s_g[0 * H4_ + 256 + tid] = a2;
            s_g[1 * H4_ + 256 + tid] = a3;
        }
        __syncthreads();   // sync C: gates ready

        // ---- LSTM cell for (n'=an, h=ak); cs still live in this thread ----
        {
            const float ai = s_g[an * H4_ + ak];
            const float af = s_g[an * H4_ + 128 + ak];
            const float ao = s_g[an * H4_ + 256 + ak];
            const float ag = s_g[an * H4_ + 384 + ak];
            const float i_ = 1.f / (1.f + expf(-ai));
            const float f_ = 1.f / (1.f + expf(-af));
            const float o_ = 1.f / (1.f + expf(-ao));
            const float gv = tanhf(ag);
            const float m  = smask[t * N_ + n0 + an];

            const float c  = m * (f_ * cs + i_ * gv);
            const float hv = m * (o_ * tanhf(c));

            hist[(size_t)t * HSTRIDE + an * H_ + ak]            = hv;
            hist[(size_t)t * HSTRIDE + NB * H_ + an * H_ + ak]  = c;
            hmean_acc += m * hv;
            len_acc   += m;
        }
        // no barrier needed here: next iter's sync A covers all reuse hazards
    }

    g_hmean[(n0 + an) * H_ + ak] = hmean_acc / len_acc;
}

// ---------------- kernel 3: out = hmean @ W_out + b_out ---------------------
#define OUT_SMEM_BYTES ((32 * 128 + 128 * 128) * 4)
__global__ __launch_bounds__(256) void out_kernel(
    const float* __restrict__ Wo, const float* __restrict__ bo,
    float* __restrict__ out)
{
    extern __shared__ float dynsmem[];
    float* As = dynsmem;               // [32][128]
    float* Bs = dynsmem + 32 * 128;    // [128][128]

    const int v0 = blockIdx.x * 128;
    const int n0 = blockIdx.y * 32;
    const int tid = threadIdx.x;

    for (int idx = tid; idx < 32 * 128; idx += 256) {
        const int r = idx >> 7, k = idx & 127;
        As[r * 128 + k] = g_hmean[(n0 + r) * H_ + k];
    }
    for (int idx4 = tid; idx4 < 4096; idx4 += 256) {
        const int k = idx4 >> 5;
        const int c4 = idx4 & 31;
        const int v = v0 + c4 * 4;
        float4 val = make_float4(0.f, 0.f, 0.f, 0.f);
        if (v < V_) val = *(const float4*)(Wo + (size_t)k * V_ + v);
        *(float4*)(Bs + k * 128 + c4 * 4) = val;
    }
    __syncthreads();

    const int tx = tid & 31;
    const int ty = tid >> 5;
    float acc[4][4] = {};

    #pragma unroll 4
    for (int k = 0; k < 128; k++) {
        float a0 = As[(ty * 4 + 0) * 128 + k];
        float a1 = As[(ty * 4 + 1) * 128 + k];
        float a2 = As[(ty * 4 + 2) * 128 + k];
        float a3 = As[(ty * 4 + 3) * 128 + k];
        float4 b4 = *(const float4*)(Bs + k * 128 + tx * 4);
        acc[0][0] += a0 * b4.x; acc[0][1] += a0 * b4.y; acc[0][2] += a0 * b4.z; acc[0][3] += a0 * b4.w;
        acc[1][0] += a1 * b4.x; acc[1][1] += a1 * b4.y; acc[1][2] += a1 * b4.z; acc[1][3] += a1 * b4.w;
        acc[2][0] += a2 * b4.x; acc[2][1] += a2 * b4.y; acc[2][2] += a2 * b4.z; acc[2][3] += a2 * b4.w;
        acc[3][0] += a3 * b4.x; acc[3][1] += a3 * b4.y; acc[3][2] += a3 * b4.z; acc[3][3] += a3 * b4.w;
    }

    #pragma unroll
    for (int i = 0; i < 4; i++) {
        const size_t n = n0 + ty * 4 + i;
        #pragma unroll
        for (int jj = 0; jj < 4; jj++) {
            const int v = v0 + tx * 4 + jj;
            if (v < V_) out[n * V_ + v] = acc[i][jj] + bo[v];
        }
    }
}

// ---------------- launch ----------------------------------------------------
extern "C" void kernel_launch(void* const* d_in, const int* in_sizes, int n_in,
                              void* d_out, int out_size)
{
    const int*   seq   = (const int*)  d_in[0];   // (T,N) int32
    const float* smask = (const float*)d_in[1];   // (T,N)
    const float* topo  = (const float*)d_in[2];   // (T,N,T)
    const float* W     = (const float*)d_in[3];   // (H,4H)
    const float* U     = (const float*)d_in[4];   // (H,4H)
    const float* b     = (const float*)d_in[5];   // (4H,)
    const float* emb   = (const float*)d_in[6];   // (V,H)
    const float* Wo    = (const float*)d_in[7];   // (H,V)
    const float* bo    = (const float*)d_in[8];   // (V,)
    float* out = (float*)d_out;                   // (N,V)

    cudaFuncSetAttribute(xw_kernel,  cudaFuncAttributeMaxDynamicSharedMemorySize, XW_SMEM_BYTES);
    cudaFuncSetAttribute(rec_kernel, cudaFuncAttributeMaxDynamicSharedMemorySize, REC_SMEM_BYTES);
    cudaFuncSetAttribute(out_kernel, cudaFuncAttributeMaxDynamicSharedMemorySize, OUT_SMEM_BYTES);

    // 1) parallel precompute of emb@W + b for all (t,n)
    xw_kernel<<<dim3((T_ * N_) / 64, H4_ / 64), 256, XW_SMEM_BYTES>>>(seq, emb, W, b);

    // 2) whole recurrence in ONE persistent kernel (per-n independence)
    rec_kernel<<<NBLK, 256, REC_SMEM_BYTES>>>(topo, smask, U);

    // 3) output projection (hmean folded into rec_kernel)
    out_kernel<<<dim3((V_ + 127) / 128, N_ / 32), 256, OUT_SMEM_BYTES>>>(Wo, bo, out);
}

// round 13
// speedup vs baseline: 2.7026x; 1.4234x over previous
#include <cuda_runtime.h>
#include <math.h>

#define T_  200
#define N_  256
#define H_  128
#define H4_ 512
#define V_  50000

#define NB   2            // batch elements per block
#define NBLK (N_ / NB)    // 128 persistent blocks

// ---------------- scratch (device globals; no runtime allocation) ----------
__device__ float  g_xw[(size_t)T_ * N_ * H4_];             // [t][n][4H]  ~105 MB
// per-block-compact history, h and c interleaved: [block][t][n'][h] -> (h,c)
__device__ float2 g_hist2[(size_t)NBLK * T_ * NB * H_];    // ~52 MB
__device__ float  g_hmean[N_ * H_];

// ============================================================================
// kernel 1: xw[t,n,:] = emb[seq[t,n]] @ W + b
// 128x128 tile, 256 threads, 8x8 register micro-tile. A tile stored K-major.
// ============================================================================
#define XW_AS_LD 132                       // padded (As is [k][r], r stride)
#define XW_SMEM_BYTES ((128 * XW_AS_LD + 128 * 128) * 4)

__global__ __launch_bounds__(256) void xw_kernel(
    const int* __restrict__ seq, const float* __restrict__ emb,
    const float* __restrict__ W, const float* __restrict__ b)
{
    extern __shared__ float dynsmem[];
    float* As = dynsmem;                    // [k][r]  (K-major, padded)
    float* Bs = dynsmem + 128 * XW_AS_LD;   // [k][j]  (row-major)

    const int r0  = blockIdx.x * 128;
    const int j0  = blockIdx.y * 128;
    const int tid = threadIdx.x;

    // ---- load A tile (gathered embedding rows), transposed into As[k][r] ----
    {
        const int r    = tid >> 1;          // 128 rows, 2 threads each
        const int half = tid & 1;           // 64 floats each
        const int s = seq[r0 + r];
        const float4* src = (const float4*)(emb + (size_t)s * H_ + half * 64);
        #pragma unroll
        for (int i = 0; i < 16; i++) {
            float4 v = src[i];
            const int k = half * 64 + i * 4;
            As[(k + 0) * XW_AS_LD + r] = v.x;
            As[(k + 1) * XW_AS_LD + r] = v.y;
            As[(k + 2) * XW_AS_LD + r] = v.z;
            As[(k + 3) * XW_AS_LD + r] = v.w;
        }
    }
    // ---- load B tile: W[k][j0 .. j0+127] ----
    {
        const int k    = tid >> 1;
        const int half = tid & 1;
        const float4* src = (const float4*)(W + (size_t)k * H4_ + j0 + half * 64);
        float4* dst = (float4*)(Bs + k * 128 + half * 64);
        #pragma unroll
        for (int i = 0; i < 16; i++) dst[i] = src[i];
    }
    __syncthreads();

    const int tx = tid & 15;    // col group (8 cols)
    const int ty = tid >> 4;    // row group (8 rows)
    float acc[8][8] = {};

    #pragma unroll 2
    for (int k = 0; k < 128; k++) {
        float4 a0 = *(const float4*)(As + k * XW_AS_LD + ty * 8);
        float4 a1 = *(const float4*)(As + k * XW_AS_LD + ty * 8 + 4);
        float4 b0 = *(const float4*)(Bs + k * 128 + tx * 8);
        float4 b1 = *(const float4*)(Bs + k * 128 + tx * 8 + 4);
        const float av[8] = {a0.x, a0.y, a0.z, a0.w, a1.x, a1.y, a1.z, a1.w};
        const float bv[8] = {b0.x, b0.y, b0.z, b0.w, b1.x, b1.y, b1.z, b1.w};
        #pragma unroll
        for (int i = 0; i < 8; i++)
            #pragma unroll
            for (int j = 0; j < 8; j++)
                acc[i][j] += av[i] * bv[j];
    }

    #pragma unroll
    for (int i = 0; i < 8; i++) {
        const size_t r = r0 + ty * 8 + i;
        #pragma unroll
        for (int jq = 0; jq < 2; jq++) {
            const int j = j0 + tx * 8 + jq * 4;
            float4 o;
            o.x = acc[i][jq * 4 + 0] + b[j + 0];
            o.y = acc[i][jq * 4 + 1] + b[j + 1];
            o.z = acc[i][jq * 4 + 2] + b[j + 2];
            o.w = acc[i][jq * 4 + 3] + b[j + 3];
            *(float4*)(g_xw + r * H4_ + j) = o;
        }
    }
}

// ============================================================================
// kernel 2: persistent recurrence (one block per NB batch elements)
// ============================================================================
#define SM_SU   (128 * 256)     // U cols 256..511
#define SM_HS   (128 * NB)
#define SM_G    (NB * H4_)
#define SM_TOPO (NB * T_)
#define SM_MASK (NB * T_)
#define REC_SMEM_BYTES ((SM_SU + SM_HS + SM_G + SM_TOPO + SM_MASK) * 4)

__global__ __launch_bounds__(256, 1) void rec_kernel(
    const float* __restrict__ topo, const float* __restrict__ smask,
    const float* __restrict__ U)
{
    extern __shared__ float sm[];
    float* sU     = sm;                    // [k][j], j -> U col 256+j
    float* s_hs   = sU + SM_SU;            // [k][NB]
    float* s_g    = s_hs + SM_HS;          // [n'][512]
    float* s_topo = s_g + SM_G;            // [n'][T_]
    float* s_mask = s_topo + SM_TOPO;      // [n'][T_]

    const int b   = blockIdx.x;
    const int tid = threadIdx.x;
    const int n0  = b * NB;
    const int an  = tid >> 7;     // n' in [0,NB)
    const int ak  = tid & 127;    // k / h index

    // ---- prologue: U (half regs, half smem), masks to smem ----
    float u[128];
    #pragma unroll
    for (int k = 0; k < 128; k++) u[k] = U[(size_t)k * H4_ + tid];
    for (int idx = tid; idx < 128 * 256; idx += 256) {
        const int k = idx >> 8, j = idx & 255;
        sU[idx] = U[(size_t)k * H4_ + 256 + j];
    }
    for (int idx = tid; idx < NB * T_; idx += 256) {
        const int nn = idx / T_, tt = idx % T_;
        s_mask[nn * T_ + tt] = smask[tt * N_ + n0 + nn];
    }

    float2* hist = g_hist2 + (size_t)b * T_ * NB * H_;   // [t][n'][h] -> (h,c)
    const int HS = NB * H_;                               // float2 stride per t

    float hmean_acc = 0.f, len_acc = 0.f;
    __syncthreads();

    for (int t = 0; t < T_; t++) {
        // ---- stage topo rows (t' < t) ----
        #pragma unroll
        for (int nn = 0; nn < NB; nn++) {
            const float* trow = topo + ((size_t)t * N_ + n0 + nn) * T_;
            for (int i = tid; i < t; i += 256) s_topo[nn * T_ + i] = trow[i];
        }
        __syncthreads();   // sync A: topo ready; also fences s_hs reuse

        // ---- prefetch this step's xw rows (independent of agg) ----
        const float* xwp = g_xw + ((size_t)t * N_ + n0) * H4_;
        float x0 = xwp[tid];
        float x1 = xwp[H4_ + tid];
        float x2 = xwp[256 + tid];
        float x3 = xwp[H4_ + 256 + tid];

        // ---- aggregation: hs/cs[n'=an, h=ak] over history (float2 loads) ----
        float hs, cs;
        {
            const float2* hp = hist + an * H_ + ak;
            const float*  tw = s_topo + an * T_;
            float h0 = 0.f, h1 = 0.f, h2 = 0.f, h3 = 0.f;
            float c0 = 0.f, c1 = 0.f, c2 = 0.f, c3 = 0.f;
            int tp = 0;
            for (; tp + 8 <= t; tp += 8) {
                float2 v0 = hp[(size_t)(tp + 0) * HS];
                float2 v1 = hp[(size_t)(tp + 1) * HS];
                float2 v2 = hp[(size_t)(tp + 2) * HS];
                float2 v3 = hp[(size_t)(tp + 3) * HS];
                float2 v4 = hp[(size_t)(tp + 4) * HS];
                float2 v5 = hp[(size_t)(tp + 5) * HS];
                float2 v6 = hp[(size_t)(tp + 6) * HS];
                float2 v7 = hp[(size_t)(tp + 7) * HS];
                float w0 = tw[tp + 0], w1 = tw[tp + 1], w2 = tw[tp + 2], w3 = tw[tp + 3];
                float w4 = tw[tp + 4], w5 = tw[tp + 5], w6 = tw[tp + 6], w7 = tw[tp + 7];
                h0 += w0 * v0.x; c0 += w0 * v0.y;
                h1 += w1 * v1.x; c1 += w1 * v1.y;
                h2 += w2 * v2.x; c2 += w2 * v2.y;
                h3 += w3 * v3.x; c3 += w3 * v3.y;
                h0 += w4 * v4.x; c0 += w4 * v4.y;
                h1 += w5 * v5.x; c1 += w5 * v5.y;
                h2 += w6 * v6.x; c2 += w6 * v6.y;
                h3 += w7 * v7.x; c3 += w7 * v7.y;
            }
            for (; tp < t; tp++) {
                float2 v = hp[(size_t)tp * HS];
                float  w = tw[tp];
                h0 += w * v.x; c0 += w * v.y;
            }
            hs = (h0 + h1) + (h2 + h3);
            cs = (c0 + c1) + (c2 + c3);
        }
        s_hs[ak * NB + an] = hs;
        __syncthreads();   // sync B: hs ready; also fences s_g reuse

        // ---- gates GEMM: cols tid (regs) and 256+tid (smem), both n' ----
        {
            float a0 = x0, a1 = x1, a2 = x2, a3 = x3;
            #pragma unroll
            for (int k = 0; k < 128; k++) {
                const float2 hv = *(const float2*)(s_hs + k * NB);
                const float  ub = sU[k * 256 + tid];
                a0 += hv.x * u[k];
                a1 += hv.y * u[k];
                a2 += hv.x * ub;
                a3 += hv.y * ub;
            }
            s_g[0 * H4_ + tid]       = a0;
            s_g[1 * H4_ + tid]       = a1;
            s_g[0 * H4_ + 256 + tid] = a2;
            s_g[1 * H4_ + 256 + tid] = a3;
        }
        __syncthreads();   // sync C: gates ready

        // ---- LSTM cell for (n'=an, h=ak); cs still live in registers ----
        {
            const float ai = s_g[an * H4_ + ak];
            const float af = s_g[an * H4_ + 128 + ak];
            const float ao = s_g[an * H4_ + 256 + ak];
            const float ag = s_g[an * H4_ + 384 + ak];
            const float i_ = 1.f / (1.f + expf(-ai));
            const float f_ = 1.f / (1.f + expf(-af));
            const float o_ = 1.f / (1.f + expf(-ao));
            const float gv = tanhf(ag);
            const float m  = s_mask[an * T_ + t];

            const float c  = m * (f_ * cs + i_ * gv);
            const float hv = m * (o_ * tanhf(c));

            hist[(size_t)t * HS + an * H_ + ak] = make_float2(hv, c);
            hmean_acc += m * hv;
            len_acc   += m;
        }
        // no extra barrier: hist element is same-thread; smem reuse fenced above
    }

    g_hmean[(n0 + an) * H_ + ak] = hmean_acc / len_acc;
}

// ============================================================================
// kernel 3: out = hmean @ W_out + b_out   (128x128 tile, 8x8 micro-tile)
// ============================================================================
#define OUT_AS_LD 132
#define OUT_SMEM_BYTES ((128 * OUT_AS_LD + 128 * 128) * 4)

__global__ __launch_bounds__(256) void out_kernel(
    const float* __restrict__ Wo, const float* __restrict__ bo,
    float* __restrict__ out)
{
    extern __shared__ float dynsmem[];
    float* As = dynsmem;                    // [k][n]  (K-major, padded)
    float* Bs = dynsmem + 128 * OUT_AS_LD;  // [k][v]

    const int v0  = blockIdx.x * 128;
    const int n0  = blockIdx.y * 128;
    const int tid = threadIdx.x;

    // ---- load A tile (hmean rows n0..n0+127), transposed ----
    {
        const int r    = tid >> 1;
        const int half = tid & 1;
        const float4* src = (const float4*)(g_hmean + (size_t)(n0 + r) * H_ + half * 64);
        #pragma unroll
        for (int i = 0; i < 16; i++) {
            float4 v = src[i];
            const int k = half * 64 + i * 4;
            As[(k + 0) * OUT_AS_LD + r] = v.x;
            As[(k + 1) * OUT_AS_LD + r] = v.y;
            As[(k + 2) * OUT_AS_LD + r] = v.z;
            As[(k + 3) * OUT_AS_LD + r] = v.w;
        }
    }
    // ---- load B tile: Wo[k][v0 .. v0+127] with V guard ----
    {
        const int k    = tid >> 1;
        const int half = tid & 1;
        #pragma unroll
        for (int i = 0; i < 16; i++) {
            const int v = v0 + half * 64 + i * 4;
            float4 val = make_float4(0.f, 0.f, 0.f, 0.f);
            if (v < V_) val = *(const float4*)(Wo + (size_t)k * V_ + v);
            *(float4*)(Bs + k * 128 + half * 64 + i * 4) = val;
        }
    }
    __syncthreads();

    const int tx = tid & 15;
    const int ty = tid >> 4;
    float acc[8][8] = {};

    #pragma unroll 2
    for (int k = 0; k < 128; k++) {
        float4 a0 = *(const float4*)(As + k * OUT_AS_LD + ty * 8);
        float4 a1 = *(const float4*)(As + k * OUT_AS_LD + ty * 8 + 4);
        float4 b0 = *(const float4*)(Bs + k * 128 + tx * 8);
        float4 b1 = *(const float4*)(Bs + k * 128 + tx * 8 + 4);
        const float av[8] = {a0.x, a0.y, a0.z, a0.w, a1.x, a1.y, a1.z, a1.w};
        const float bv[8] = {b0.x, b0.y, b0.z, b0.w, b1.x, b1.y, b1.z, b1.w};
        #pragma unroll
        for (int i = 0; i < 8; i++)
            #pragma unroll
            for (int j = 0; j < 8; j++)
                acc[i][j] += av[i] * bv[j];
    }

    #pragma unroll
    for (int i = 0; i < 8; i++) {
        const size_t n = n0 + ty * 8 + i;
        #pragma unroll
        for (int jq = 0; jq < 2; jq++) {
            const int v = v0 + tx * 8 + jq * 4;
            if (v < V_) {   // V_ % 4 == 0, so whole float4 is in/out together
                float4 o;
                o.x = acc[i][jq * 4 + 0] + bo[v + 0];
                o.y = acc[i][jq * 4 + 1] + bo[v + 1];
                o.z = acc[i][jq * 4 + 2] + bo[v + 2];
                o.w = acc[i][jq * 4 + 3] + bo[v + 3];
                *(float4*)(out + n * V_ + v) = o;
            }
        }
    }
}

// ---------------- launch ----------------------------------------------------
extern "C" void kernel_launch(void* const* d_in, const int* in_sizes, int n_in,
                              void* d_out, int out_size)
{
    const int*   seq   = (const int*)  d_in[0];   // (T,N) int32
    const float* smask = (const float*)d_in[1];   // (T,N)
    const float* topo  = (const float*)d_in[2];   // (T,N,T)
    const float* W     = (const float*)d_in[3];   // (H,4H)
    const float* U     = (const float*)d_in[4];   // (H,4H)
    const float* b     = (const float*)d_in[5];   // (4H,)
    const float* emb   = (const float*)d_in[6];   // (V,H)
    const float* Wo    = (const float*)d_in[7];   // (H,V)
    const float* bo    = (const float*)d_in[8];   // (V,)
    float* out = (float*)d_out;                   // (N,V)

    cudaFuncSetAttribute(xw_kernel,  cudaFuncAttributeMaxDynamicSharedMemorySize, XW_SMEM_BYTES);
    cudaFuncSetAttribute(rec_kernel, cudaFuncAttributeMaxDynamicSharedMemorySize, REC_SMEM_BYTES);
    cudaFuncSetAttribute(out_kernel, cudaFuncAttributeMaxDynamicSharedMemorySize, OUT_SMEM_BYTES);

    // 1) parallel precompute of emb@W + b for all (t,n)
    xw_kernel<<<dim3((T_ * N_) / 128, H4_ / 128), 256, XW_SMEM_BYTES>>>(seq, emb, W, b);

    // 2) whole recurrence in ONE persistent kernel (per-n independence)
    rec_kernel<<<NBLK, 256, REC_SMEM_BYTES>>>(topo, smask, U);

    // 3) output projection (hmean folded into rec_kernel)
    out_kernel<<<dim3((V_ + 127) / 128, (N_ + 127) / 128), 256, OUT_SMEM_BYTES>>>(Wo, bo, out);
}

// round 14
// speedup vs baseline: 2.7887x; 1.0319x over previous
#include <cuda_runtime.h>
#include <math.h>

#define T_  200
#define N_  256
#define H_  128
#define H4_ 512
#define V_  50000

#define NB   2            // batch elements per block
#define NBLK (N_ / NB)    // 128 persistent blocks

// ---------------- scratch (device globals; no runtime allocation) ----------
__device__ float  g_xw[(size_t)T_ * N_ * H4_];             // [t][n][4H]  ~105 MB
// per-block-compact history, h and c interleaved: [block][t][n'][h] -> (h,c)
__device__ float2 g_hist2[(size_t)NBLK * T_ * NB * H_];    // ~52 MB
__device__ float  g_hmean[N_ * H_];

// ============================================================================
// kernel 1: xw[t,n,:] = emb[seq[t,n]] @ W + b
// 128x128 tile, split-K (2 x 64) for 66.5KB smem -> 2 CTAs/SM, 8x8 micro-tile
// ============================================================================
#define XW_AS_LD 132
#define XW_SMEM_BYTES ((64 * XW_AS_LD + 64 * 128) * 4)

__global__ __launch_bounds__(256) void xw_kernel(
    const int* __restrict__ seq, const float* __restrict__ emb,
    const float* __restrict__ W, const float* __restrict__ b)
{
    extern __shared__ float dynsmem[];
    float* As = dynsmem;                   // [k<64][r<128]  K-major, padded
    float* Bs = dynsmem + 64 * XW_AS_LD;   // [k<64][j<128]

    const int r0  = blockIdx.x * 128;
    const int j0  = blockIdx.y * 128;
    const int tid = threadIdx.x;

    const int ar   = tid >> 1;          // A: row 0..127
    const int ah   = tid & 1;           // A: 32-col half within phase
    const int bk   = tid >> 2;          // B: k row 0..63
    const int bq   = tid & 3;           // B: 32-col quarter
    const int s    = seq[r0 + ar];

    const int tx = tid & 15;
    const int ty = tid >> 4;
    float acc[8][8] = {};

    #pragma unroll
    for (int ks = 0; ks < 2; ks++) {
        if (ks) __syncthreads();   // protect smem reuse between phases

        // A half: emb[s][ks*64 + ah*32 .. +32) -> As[k_local][r]
        {
            const float4* src = (const float4*)(emb + (size_t)s * H_ + ks * 64 + ah * 32);
            #pragma unroll
            for (int i = 0; i < 8; i++) {
                float4 v = src[i];
                const int k = ah * 32 + i * 4;
                As[(k + 0) * XW_AS_LD + ar] = v.x;
                As[(k + 1) * XW_AS_LD + ar] = v.y;
                As[(k + 2) * XW_AS_LD + ar] = v.z;
                As[(k + 3) * XW_AS_LD + ar] = v.w;
            }
        }
        // B half: W[ks*64 + bk][j0 + bq*32 .. +32)
        {
            const float4* src = (const float4*)(W + (size_t)(ks * 64 + bk) * H4_ + j0 + bq * 32);
            float4* dst = (float4*)(Bs + bk * 128 + bq * 32);
            #pragma unroll
            for (int i = 0; i < 8; i++) dst[i] = src[i];
        }
        __syncthreads();

        #pragma unroll 2
        for (int k = 0; k < 64; k++) {
            float4 a0 = *(const float4*)(As + k * XW_AS_LD + ty * 8);
            float4 a1 = *(const float4*)(As + k * XW_AS_LD + ty * 8 + 4);
            float4 b0 = *(const float4*)(Bs + k * 128 + tx * 8);
            float4 b1 = *(const float4*)(Bs + k * 128 + tx * 8 + 4);
            const float av[8] = {a0.x, a0.y, a0.z, a0.w, a1.x, a1.y, a1.z, a1.w};
            const float bv[8] = {b0.x, b0.y, b0.z, b0.w, b1.x, b1.y, b1.z, b1.w};
            #pragma unroll
            for (int i = 0; i < 8; i++)
                #pragma unroll
                for (int j = 0; j < 8; j++)
                    acc[i][j] += av[i] * bv[j];
        }
    }

    #pragma unroll
    for (int i = 0; i < 8; i++) {
        const size_t r = r0 + ty * 8 + i;
        #pragma unroll
        for (int jq = 0; jq < 2; jq++) {
            const int j = j0 + tx * 8 + jq * 4;
            float4 o;
            o.x = acc[i][jq * 4 + 0] + b[j + 0];
            o.y = acc[i][jq * 4 + 1] + b[j + 1];
            o.z = acc[i][jq * 4 + 2] + b[j + 2];
            o.w = acc[i][jq * 4 + 3] + b[j + 3];
            *(float4*)(g_xw + r * H4_ + j) = o;
        }
    }
}

// ============================================================================
// kernel 2: persistent recurrence, software-pipelined:
//   region 1 (long): agg for step t+1 over [0,t)  +  gates GEMM for step t
//   region 2 (short): cell for t, add last agg term from registers, stage topo
// Only 2 barriers per step; agg L2 latency overlaps gates FMA across warps.
// ============================================================================
#define SM_SU   (128 * 256)     // U cols 256..511
#define SM_HS   (128 * NB)
#define SM_G    (NB * H4_)
#define SM_TB   (NB * T_)       // one topo buffer
#define SM_MASK (NB * T_)
#define REC_SMEM_BYTES ((SM_SU + SM_HS + SM_G + 2 * SM_TB + SM_MASK) * 4)

__global__ __launch_bounds__(256, 1) void rec_kernel(
    const float* __restrict__ topo, const float* __restrict__ smask,
    const float* __restrict__ U)
{
    extern __shared__ float sm[];
    float* sU     = sm;                    // [k][j], j -> U col 256+j
    float* s_hs   = sU + SM_SU;            // [k][NB]
    float* s_g    = s_hs + SM_HS;          // [n'][512]
    float* s_topo = s_g + SM_G;            // [2][n'][T_]  (double buffer)
    float* s_mask = s_topo + 2 * SM_TB;    // [n'][T_]

    const int b   = blockIdx.x;
    const int tid = threadIdx.x;
    const int n0  = b * NB;
    const int an  = tid >> 7;     // n' in [0,NB)
    const int ak  = tid & 127;    // k / h index

    // ---- prologue ----
    float u[128];
    #pragma unroll
    for (int k = 0; k < 128; k++) u[k] = U[(size_t)k * H4_ + tid];
    for (int idx = tid; idx < 128 * 256; idx += 256) {
        const int k = idx >> 8, j = idx & 255;
        sU[idx] = U[(size_t)k * H4_ + 256 + j];
    }
    for (int idx = tid; idx < NB * T_; idx += 256) {
        const int nn = idx / T_, tt = idx % T_;
        s_mask[nn * T_ + tt] = smask[tt * N_ + n0 + nn];
    }
    s_hs[tid] = 0.f;                       // h_sum for step 0 is zero
    // stage topo row 1 into buffer parity 1 (needs entry 0 only)
    #pragma unroll
    for (int nn = 0; nn < NB; nn++) {
        const float* trow = topo + ((size_t)1 * N_ + n0 + nn) * T_;
        for (int i = tid; i < 2; i += 256) s_topo[1 * SM_TB + nn * T_ + i] = trow[i];
    }

    float2* hist = g_hist2 + (size_t)b * T_ * NB * H_;   // [t][n'][h] -> (h,c)
    const int HS = NB * H_;

    float cs_cur = 0.f;                    // c_sum for current step (t=0: empty)
    float hmean_acc = 0.f, len_acc = 0.f;
    __syncthreads();                       // barrier alpha for iter 0

    for (int t = 0; t < T_; t++) {
        const bool more = (t + 1 < T_);

        // ---- prefetch this step's xw rows (DRAM latency hides under region 1) ----
        const float* xwp = g_xw + ((size_t)t * N_ + n0) * H4_;
        float x0 = xwp[tid];
        float x1 = xwp[H4_ + tid];
        float x2 = xwp[256 + tid];
        float x3 = xwp[H4_ + 256 + tid];

        // ---- agg for step t+1 over t' in [0, t)  (L2-latency bound) ----
        float hs_nx = 0.f, cs_nx = 0.f;
        if (more) {
            const float2* hp = hist + an * H_ + ak;
            const float*  tw = s_topo + ((t + 1) & 1) * SM_TB + an * T_;
            float h0 = 0.f, h1 = 0.f, h2 = 0.f, h3 = 0.f;
            float c0 = 0.f, c1 = 0.f, c2 = 0.f, c3 = 0.f;
            int tp = 0;
            for (; tp + 8 <= t; tp += 8) {
                float2 v0 = hp[(size_t)(tp + 0) * HS];
                float2 v1 = hp[(size_t)(tp + 1) * HS];
                float2 v2 = hp[(size_t)(tp + 2) * HS];
                float2 v3 = hp[(size_t)(tp + 3) * HS];
                float2 v4 = hp[(size_t)(tp + 4) * HS];
                float2 v5 = hp[(size_t)(tp + 5) * HS];
                float2 v6 = hp[(size_t)(tp + 6) * HS];
                float2 v7 = hp[(size_t)(tp + 7) * HS];
                float w0 = tw[tp + 0], w1 = tw[tp + 1], w2 = tw[tp + 2], w3 = tw[tp + 3];
                float w4 = tw[tp + 4], w5 = tw[tp + 5], w6 = tw[tp + 6], w7 = tw[tp + 7];
                h0 += w0 * v0.x; c0 += w0 * v0.y;
                h1 += w1 * v1.x; c1 += w1 * v1.y;
                h2 += w2 * v2.x; c2 += w2 * v2.y;
                h3 += w3 * v3.x; c3 += w3 * v3.y;
                h0 += w4 * v4.x; c0 += w4 * v4.y;
                h1 += w5 * v5.x; c1 += w5 * v5.y;
                h2 += w6 * v6.x; c2 += w6 * v6.y;
                h3 += w7 * v7.x; c3 += w7 * v7.y;
            }
            for (; tp < t; tp++) {
                float2 v = hp[(size_t)tp * HS];
                float  w = tw[tp];
                h0 += w * v.x; c0 += w * v.y;
            }
            hs_nx = (h0 + h1) + (h2 + h3);
            cs_nx = (c0 + c1) + (c2 + c3);
        }

        // ---- gates GEMM for step t (FMA bound; overlaps agg across warps) ----
        {
            float a0 = x0, a1 = x1, a2 = x2, a3 = x3;
            #pragma unroll
            for (int k = 0; k < 128; k++) {
                const float2 hv = *(const float2*)(s_hs + k * NB);
                const float  ub = sU[k * 256 + tid];
                a0 += hv.x * u[k];
                a1 += hv.y * u[k];
                a2 += hv.x * ub;
                a3 += hv.y * ub;
            }
            s_g[0 * H4_ + tid]       = a0;
            s_g[1 * H4_ + tid]       = a1;
            s_g[0 * H4_ + 256 + tid] = a2;
            s_g[1 * H4_ + 256 + tid] = a3;
        }
        __syncthreads();   // barrier beta: s_g ready; s_hs reads complete

        // ---- region 2: cell for t, last agg term from registers ----
        {
            const float ai = s_g[an * H4_ + ak];
            const float af = s_g[an * H4_ + 128 + ak];
            const float ao = s_g[an * H4_ + 256 + ak];
            const float ag = s_g[an * H4_ + 384 + ak];
            const float i_ = 1.f / (1.f + expf(-ai));
            const float f_ = 1.f / (1.f + expf(-af));
            const float o_ = 1.f / (1.f + expf(-ao));
            const float gv = tanhf(ag);
            const float m  = s_mask[an * T_ + t];

            const float c  = m * (f_ * cs_cur + i_ * gv);
            const float hv = m * (o_ * tanhf(c));

            hist[(size_t)t * HS + an * H_ + ak] = make_float2(hv, c);
            hmean_acc += m * hv;
            len_acc   += m;

            if (more) {
                // last term (t' = t) of step-(t+1) aggregation: pure registers
                const float w = s_topo[((t + 1) & 1) * SM_TB + an * T_ + t];
                hs_nx += w * hv;
                cs_nx += w * c;
                s_hs[ak * NB + an] = hs_nx;
            }
            cs_cur = cs_nx;
        }

        // ---- stage topo row t+2 into buffer parity t&1 (needs entries < t+2) ----
        if (t + 2 < T_) {
            #pragma unroll
            for (int nn = 0; nn < NB; nn++) {
                const float* trow = topo + ((size_t)(t + 2) * N_ + n0 + nn) * T_;
                for (int i = tid; i < t + 2; i += 256)
                    s_topo[(t & 1) * SM_TB + nn * T_ + i] = trow[i];
            }
        }
        __syncthreads();   // barrier alpha: s_hs / s_topo ready for next iter
    }

    g_hmean[(n0 + an) * H_ + ak] = hmean_acc / len_acc;
}

// ============================================================================
// kernel 3: out = hmean @ W_out + b_out
// 128x128 tile, split-K (2 x 64) -> 66.5KB smem -> 2 CTAs/SM, 8x8 micro-tile
// ============================================================================
#define OUT_AS_LD 132
#define OUT_SMEM_BYTES ((64 * OUT_AS_LD + 64 * 128) * 4)

__global__ __launch_bounds__(256) void out_kernel(
    const float* __restrict__ Wo, const float* __restrict__ bo,
    float* __restrict__ out)
{
    extern __shared__ float dynsmem[];
    float* As = dynsmem;                    // [k<64][n<128]
    float* Bs = dynsmem + 64 * OUT_AS_LD;   // [k<64][v<128]

    const int v0  = blockIdx.x * 128;
    const int n0  = blockIdx.y * 128;
    const int tid = threadIdx.x;

    const int ar = tid >> 1;
    const int ah = tid & 1;
    const int bk = tid >> 2;
    const int bq = tid & 3;

    const int tx = tid & 15;
    const int ty = tid >> 4;
    float acc[8][8] = {};

    #pragma unroll
    for (int ks = 0; ks < 2; ks++) {
        if (ks) __syncthreads();

        // A half: hmean[n0+ar][ks*64 + ah*32 .. +32)
        {
            const float4* src = (const float4*)(g_hmean + (size_t)(n0 + ar) * H_ + ks * 64 + ah * 32);
            #pragma unroll
            for (int i = 0; i < 8; i++) {
                float4 v = src[i];
                const int k = ah * 32 + i * 4;
                As[(k + 0) * OUT_AS_LD + ar] = v.x;
                As[(k + 1) * OUT_AS_LD + ar] = v.y;
                As[(k + 2) * OUT_AS_LD + ar] = v.z;
                As[(k + 3) * OUT_AS_LD + ar] = v.w;
            }
        }
        // B half: Wo[ks*64 + bk][v0 + bq*32 .. +32) with V guard
        {
            #pragma unroll
            for (int i = 0; i < 8; i++) {
                const int v = v0 + bq * 32 + i * 4;
                float4 val = make_float4(0.f, 0.f, 0.f, 0.f);
                if (v < V_) val = *(const float4*)(Wo + (size_t)(ks * 64 + bk) * V_ + v);
                *(float4*)(Bs + bk * 128 + bq * 32 + i * 4) = val;
            }
        }
        __syncthreads();

        #pragma unroll 2
        for (int k = 0; k < 64; k++) {
            float4 a0 = *(const float4*)(As + k * OUT_AS_LD + ty * 8);
            float4 a1 = *(const float4*)(As + k * OUT_AS_LD + ty * 8 + 4);
            float4 b0 = *(const float4*)(Bs + k * 128 + tx * 8);
            float4 b1 = *(const float4*)(Bs + k * 128 + tx * 8 + 4);
            const float av[8] = {a0.x, a0.y, a0.z, a0.w, a1.x, a1.y, a1.z, a1.w};
            const float bv[8] = {b0.x, b0.y, b0.z, b0.w, b1.x, b1.y, b1.z, b1.w};
            #pragma unroll
            for (int i = 0; i < 8; i++)
                #pragma unroll
                for (int j = 0; j < 8; j++)
                    acc[i][j] += av[i] * bv[j];
        }
    }

    #pragma unroll
    for (int i = 0; i < 8; i++) {
        const size_t n = n0 + ty * 8 + i;
        #pragma unroll
        for (int jq = 0; jq < 2; jq++) {
            const int v = v0 + tx * 8 + jq * 4;
            if (v < V_) {   // V_ % 4 == 0 so the whole float4 is in/out together
                float4 o;
                o.x = acc[i][jq * 4 + 0] + bo[v + 0];
                o.y = acc[i][jq * 4 + 1] + bo[v + 1];
                o.z = acc[i][jq * 4 + 2] + bo[v + 2];
                o.w = acc[i][jq * 4 + 3] + bo[v + 3];
                *(float4*)(out + n * V_ + v) = o;
            }
        }
    }
}

// ---------------- launch ----------------------------------------------------
extern "C" void kernel_launch(void* const* d_in, const int* in_sizes, int n_in,
                              void* d_out, int out_size)
{
    const int*   seq   = (const int*)  d_in[0];   // (T,N) int32
    const float* smask = (const float*)d_in[1];   // (T,N)
    const float* topo  = (const float*)d_in[2];   // (T,N,T)
    const float* W     = (const float*)d_in[3];   // (H,4H)
    const float* U     = (const float*)d_in[4];   // (H,4H)
    const float* b     = (const float*)d_in[5];   // (4H,)
    const float* emb   = (const float*)d_in[6];   // (V,H)
    const float* Wo    = (const float*)d_in[7];   // (H,V)
    const float* bo    = (const float*)d_in[8];   // (V,)
    float* out = (float*)d_out;                   // (N,V)

    cudaFuncSetAttribute(xw_kernel,  cudaFuncAttributeMaxDynamicSharedMemorySize, XW_SMEM_BYTES);
    cudaFuncSetAttribute(rec_kernel, cudaFuncAttributeMaxDynamicSharedMemorySize, REC_SMEM_BYTES);
    cudaFuncSetAttribute(out_kernel, cudaFuncAttributeMaxDynamicSharedMemorySize, OUT_SMEM_BYTES);

    // 1) parallel precompute of emb@W + b for all (t,n)
    xw_kernel<<<dim3((T_ * N_) / 128, H4_ / 128), 256, XW_SMEM_BYTES>>>(seq, emb, W, b);

    // 2) whole recurrence in ONE persistent kernel (per-n independence)
    rec_kernel<<<NBLK, 256, REC_SMEM_BYTES>>>(topo, smask, U);

    // 3) output projection (hmean folded into rec_kernel)
    out_kernel<<<dim3((V_ + 127) / 128, (N_ + 127) / 128), 256, OUT_SMEM_BYTES>>>(Wo, bo, out);
}

// round 15
// speedup vs baseline: 3.6290x; 1.3013x over previous
#include <cuda_runtime.h>
#include <math.h>

#define T_  200
#define N_  256
#define H_  128
#define H4_ 512
#define V_  50000

#define NB   2            // batch elements per block
#define NBLK (N_ / NB)    // 128 persistent blocks
#define KC   44           // history steps cached in smem (2KB each)

// ---------------- scratch (device globals; no runtime allocation) ----------
__device__ float  g_xw[(size_t)T_ * N_ * H4_];             // [t][n][4H]  ~105 MB
// per-block-compact history (only t >= KC used), h,c interleaved
__device__ float2 g_hist2[(size_t)NBLK * T_ * NB * H_];    // ~52 MB
__device__ float  g_hmean[N_ * H_];

// ============================================================================
// kernel 1: xw[t,n,:] = emb[seq[t,n]] @ W + b
// 128x128 tile, split-K (2 x 64) for 66.5KB smem -> 2 CTAs/SM, 8x8 micro-tile
// ============================================================================
#define XW_AS_LD 132
#define XW_SMEM_BYTES ((64 * XW_AS_LD + 64 * 128) * 4)

__global__ __launch_bounds__(256) void xw_kernel(
    const int* __restrict__ seq, const float* __restrict__ emb,
    const float* __restrict__ W, const float* __restrict__ b)
{
    extern __shared__ float dynsmem[];
    float* As = dynsmem;                   // [k<64][r<128]  K-major, padded
    float* Bs = dynsmem + 64 * XW_AS_LD;   // [k<64][j<128]

    const int r0  = blockIdx.x * 128;
    const int j0  = blockIdx.y * 128;
    const int tid = threadIdx.x;

    const int ar = tid >> 1;
    const int ah = tid & 1;
    const int bk = tid >> 2;
    const int bq = tid & 3;
    const int s  = seq[r0 + ar];

    const int tx = tid & 15;
    const int ty = tid >> 4;
    float acc[8][8] = {};

    #pragma unroll
    for (int ks = 0; ks < 2; ks++) {
        if (ks) __syncthreads();

        {
            const float4* src = (const float4*)(emb + (size_t)s * H_ + ks * 64 + ah * 32);
            #pragma unroll
            for (int i = 0; i < 8; i++) {
                float4 v = src[i];
                const int k = ah * 32 + i * 4;
                As[(k + 0) * XW_AS_LD + ar] = v.x;
                As[(k + 1) * XW_AS_LD + ar] = v.y;
                As[(k + 2) * XW_AS_LD + ar] = v.z;
                As[(k + 3) * XW_AS_LD + ar] = v.w;
            }
        }
        {
            const float4* src = (const float4*)(W + (size_t)(ks * 64 + bk) * H4_ + j0 + bq * 32);
            float4* dst = (float4*)(Bs + bk * 128 + bq * 32);
            #pragma unroll
            for (int i = 0; i < 8; i++) dst[i] = src[i];
        }
        __syncthreads();

        #pragma unroll 2
        for (int k = 0; k < 64; k++) {
            float4 a0 = *(const float4*)(As + k * XW_AS_LD + ty * 8);
            float4 a1 = *(const float4*)(As + k * XW_AS_LD + ty * 8 + 4);
            float4 b0 = *(const float4*)(Bs + k * 128 + tx * 8);
            float4 b1 = *(const float4*)(Bs + k * 128 + tx * 8 + 4);
            const float av[8] = {a0.x, a0.y, a0.z, a0.w, a1.x, a1.y, a1.z, a1.w};
            const float bv[8] = {b0.x, b0.y, b0.z, b0.w, b1.x, b1.y, b1.z, b1.w};
            #pragma unroll
            for (int i = 0; i < 8; i++)
                #pragma unroll
                for (int j = 0; j < 8; j++)
                    acc[i][j] += av[i] * bv[j];
        }
    }

    #pragma unroll
    for (int i = 0; i < 8; i++) {
        const size_t r = r0 + ty * 8 + i;
        #pragma unroll
        for (int jq = 0; jq < 2; jq++) {
            const int j = j0 + tx * 8 + jq * 4;
            float4 o;
            o.x = acc[i][jq * 4 + 0] + b[j + 0];
            o.y = acc[i][jq * 4 + 1] + b[j + 1];
            o.z = acc[i][jq * 4 + 2] + b[j + 2];
            o.w = acc[i][jq * 4 + 3] + b[j + 3];
            *(float4*)(g_xw + r * H4_ + j) = o;
        }
    }
}

// ============================================================================
// kernel 2: persistent recurrence, pipelined, with smem history cache:
//   - first KC steps of (h,c) history live in smem (LDS, latency-free)
//   - global history loads use MLP=16 batches
//   - topo staging at top of region 1 (latency hidden under agg+gates)
// ============================================================================
#define SM_SU   (128 * 256)     // U cols 256..511
#define SM_HS   (128 * NB)
#define SM_G    (NB * H4_)
#define SM_TB   (NB * T_)
#define SM_MASK (NB * T_)
#define SM_HIST (KC * NB * H_ * 2)    // float count (float2 per element)
#define REC_SMEM_BYTES ((SM_SU + SM_HS + SM_G + 2 * SM_TB + SM_MASK + SM_HIST) * 4)

__global__ __launch_bounds__(256, 1) void rec_kernel(
    const float* __restrict__ topo, const float* __restrict__ smask,
    const float* __restrict__ U)
{
    extern __shared__ float sm[];
    float*  sU     = sm;                    // [k][j], j -> U col 256+j
    float*  s_hs   = sU + SM_SU;            // [k][NB]
    float*  s_g    = s_hs + SM_HS;          // [n'][512]
    float*  s_topo = s_g + SM_G;            // [2][n'][T_]
    float*  s_mask = s_topo + 2 * SM_TB;    // [n'][T_]
    float2* s_hist = (float2*)(s_mask + SM_MASK);   // [KC][n'][H] -> (h,c)

    const int b   = blockIdx.x;
    const int tid = threadIdx.x;
    const int n0  = b * NB;
    const int an  = tid >> 7;
    const int ak  = tid & 127;

    // ---- prologue ----
    float u[128];
    #pragma unroll
    for (int k = 0; k < 128; k++) u[k] = U[(size_t)k * H4_ + tid];
    for (int idx = tid; idx < 128 * 256; idx += 256) {
        const int k = idx >> 8, j = idx & 255;
        sU[idx] = U[(size_t)k * H4_ + 256 + j];
    }
    for (int idx = tid; idx < NB * T_; idx += 256) {
        const int nn = idx / T_, tt = idx % T_;
        s_mask[nn * T_ + tt] = smask[tt * N_ + n0 + nn];
    }
    s_hs[tid] = 0.f;
    #pragma unroll
    for (int nn = 0; nn < NB; nn++) {
        const float* trow = topo + ((size_t)1 * N_ + n0 + nn) * T_;
        for (int i = tid; i < 2; i += 256) s_topo[1 * SM_TB + nn * T_ + i] = trow[i];
    }

    float2* hist = g_hist2 + (size_t)b * T_ * NB * H_;
    const int HS = NB * H_;                // float2 stride per step

    float cs_cur = 0.f;
    float hmean_acc = 0.f, len_acc = 0.f;
    __syncthreads();                       // barrier alpha for iter 0

    for (int t = 0; t < T_; t++) {
        const bool more = (t + 1 < T_);

        // ---- prefetch this step's xw rows ----
        const float* xwp = g_xw + ((size_t)t * N_ + n0) * H4_;
        float x0 = xwp[tid];
        float x1 = xwp[H4_ + tid];
        float x2 = xwp[256 + tid];
        float x3 = xwp[H4_ + 256 + tid];

        // ---- stage topo row t+2 into parity t&1 (early: latency hides) ----
        if (t + 2 < T_) {
            #pragma unroll
            for (int nn = 0; nn < NB; nn++) {
                const float* trow = topo + ((size_t)(t + 2) * N_ + n0 + nn) * T_;
                for (int i = tid; i < t + 2; i += 256)
                    s_topo[(t & 1) * SM_TB + nn * T_ + i] = trow[i];
            }
        }

        // ---- agg for step t+1 over t' in [0, t) ----
        float hs_nx = 0.f, cs_nx = 0.f;
        if (more) {
            const float* tw = s_topo + ((t + 1) & 1) * SM_TB + an * T_;
            float h0 = 0.f, h1 = 0.f, h2 = 0.f, h3 = 0.f;
            float c0 = 0.f, c1 = 0.f, c2 = 0.f, c3 = 0.f;

            // --- smem-cached portion: t' in [0, min(t,KC)) ---
            const int tc = (t < KC) ? t : KC;
            const float2* sp = s_hist + an * H_ + ak;
            int tp = 0;
            for (; tp + 4 <= tc; tp += 4) {
                float2 v0 = sp[(tp + 0) * HS];
                float2 v1 = sp[(tp + 1) * HS];
                float2 v2 = sp[(tp + 2) * HS];
                float2 v3 = sp[(tp + 3) * HS];
                float w0 = tw[tp + 0], w1 = tw[tp + 1];
                float w2 = tw[tp + 2], w3 = tw[tp + 3];
                h0 += w0 * v0.x; c0 += w0 * v0.y;
                h1 += w1 * v1.x; c1 += w1 * v1.y;
                h2 += w2 * v2.x; c2 += w2 * v2.y;
                h3 += w3 * v3.x; c3 += w3 * v3.y;
            }
            for (; tp < tc; tp++) {
                float2 v = sp[tp * HS];
                float  w = tw[tp];
                h0 += w * v.x; c0 += w * v.y;
            }

            // --- global portion: t' in [KC, t), MLP=16 batches ---
            const float2* hp = hist + an * H_ + ak;
            for (; tp + 16 <= t; tp += 16) {
                float2 v[16];
                #pragma unroll
                for (int i = 0; i < 16; i++) v[i] = hp[(size_t)(tp + i) * HS];
                #pragma unroll
                for (int i = 0; i < 16; i++) {
                    const float w = tw[tp + i];
                    switch (i & 3) {
                        case 0: h0 += w * v[i].x; c0 += w * v[i].y; break;
                        case 1: h1 += w * v[i].x; c1 += w * v[i].y; break;
                        case 2: h2 += w * v[i].x; c2 += w * v[i].y; break;
                        default: h3 += w * v[i].x; c3 += w * v[i].y; break;
                    }
                }
            }
            for (; tp < t; tp++) {
                float2 v = hp[(size_t)tp * HS];
                float  w = tw[tp];
                h0 += w * v.x; c0 += w * v.y;
            }
            hs_nx = (h0 + h1) + (h2 + h3);
            cs_nx = (c0 + c1) + (c2 + c3);
        }

        // ---- gates GEMM for step t ----
        {
            float a0 = x0, a1 = x1, a2 = x2, a3 = x3;
            #pragma unroll
            for (int k = 0; k < 128; k++) {
                const float2 hv = *(const float2*)(s_hs + k * NB);
                const float  ub = sU[k * 256 + tid];
                a0 += hv.x * u[k];
                a1 += hv.y * u[k];
                a2 += hv.x * ub;
                a3 += hv.y * ub;
            }
            s_g[0 * H4_ + tid]       = a0;
            s_g[1 * H4_ + tid]       = a1;
            s_g[0 * H4_ + 256 + tid] = a2;
            s_g[1 * H4_ + 256 + tid] = a3;
        }
        __syncthreads();   // barrier beta: s_g ready; s_hs reads complete

        // ---- region 2: cell for t, last agg term from registers ----
        {
            const float ai = s_g[an * H4_ + ak];
            const float af = s_g[an * H4_ + 128 + ak];
            const float ao = s_g[an * H4_ + 256 + ak];
            const float ag = s_g[an * H4_ + 384 + ak];
            const float i_ = 1.f / (1.f + expf(-ai));
            const float f_ = 1.f / (1.f + expf(-af));
            const float o_ = 1.f / (1.f + expf(-ao));
            const float gv = tanhf(ag);
            const float m  = s_mask[an * T_ + t];

            const float c  = m * (f_ * cs_cur + i_ * gv);
            const float hv = m * (o_ * tanhf(c));

            if (t < KC) s_hist[t * HS + an * H_ + ak] = make_float2(hv, c);
            else        hist [(size_t)t * HS + an * H_ + ak] = make_float2(hv, c);
            hmean_acc += m * hv;
            len_acc   += m;

            if (more) {
                const float w = s_topo[((t + 1) & 1) * SM_TB + an * T_ + t];
                hs_nx += w * hv;
                cs_nx += w * c;
                s_hs[ak * NB + an] = hs_nx;
            }
            cs_cur = cs_nx;
        }
        __syncthreads();   // barrier alpha: s_hs / s_topo / s_hist ready
    }

    g_hmean[(n0 + an) * H_ + ak] = hmean_acc / len_acc;
}

// ============================================================================
// kernel 3: out = hmean @ W_out + b_out
// 128x128 tile, split-K (2 x 64) -> 66.5KB smem -> 2 CTAs/SM, 8x8 micro-tile
// ============================================================================
#define OUT_AS_LD 132
#define OUT_SMEM_BYTES ((64 * OUT_AS_LD + 64 * 128) * 4)

__global__ __launch_bounds__(256) void out_kernel(
    const float* __restrict__ Wo, const float* __restrict__ bo,
    float* __restrict__ out)
{
    extern __shared__ float dynsmem[];
    float* As = dynsmem;                    // [k<64][n<128]
    float* Bs = dynsmem + 64 * OUT_AS_LD;   // [k<64][v<128]

    const int v0  = blockIdx.x * 128;
    const int n0  = blockIdx.y * 128;
    const int tid = threadIdx.x;

    const int ar = tid >> 1;
    const int ah = tid & 1;
    const int bk = tid >> 2;
    const int bq = tid & 3;

    const int tx = tid & 15;
    const int ty = tid >> 4;
    float acc[8][8] = {};

    #pragma unroll
    for (int ks = 0; ks < 2; ks++) {
        if (ks) __syncthreads();

        {
            const float4* src = (const float4*)(g_hmean + (size_t)(n0 + ar) * H_ + ks * 64 + ah * 32);
            #pragma unroll
            for (int i = 0; i < 8; i++) {
                float4 v = src[i];
                const int k = ah * 32 + i * 4;
                As[(k + 0) * OUT_AS_LD + ar] = v.x;
                As[(k + 1) * OUT_AS_LD + ar] = v.y;
                As[(k + 2) * OUT_AS_LD + ar] = v.z;
                As[(k + 3) * OUT_AS_LD + ar] = v.w;
            }
        }
        {
            #pragma unroll
            for (int i = 0; i < 8; i++) {
                const int v = v0 + bq * 32 + i * 4;
                float4 val = make_float4(0.f, 0.f, 0.f, 0.f);
                if (v < V_) val = *(const float4*)(Wo + (size_t)(ks * 64 + bk) * V_ + v);
                *(float4*)(Bs + bk * 128 + bq * 32 + i * 4) = val;
            }
        }
        __syncthreads();

        #pragma unroll 2
        for (int k = 0; k < 64; k++) {
            float4 a0 = *(const float4*)(As + k * OUT_AS_LD + ty * 8);
            float4 a1 = *(const float4*)(As + k * OUT_AS_LD + ty * 8 + 4);
            float4 b0 = *(const float4*)(Bs + k * 128 + tx * 8);
            float4 b1 = *(const float4*)(Bs + k * 128 + tx * 8 + 4);
            const float av[8] = {a0.x, a0.y, a0.z, a0.w, a1.x, a1.y, a1.z, a1.w};
            const float bv[8] = {b0.x, b0.y, b0.z, b0.w, b1.x, b1.y, b1.z, b1.w};
            #pragma unroll
            for (int i = 0; i < 8; i++)
                #pragma unroll
                for (int j = 0; j < 8; j++)
                    acc[i][j] += av[i] * bv[j];
        }
    }

    #pragma unroll
    for (int i = 0; i < 8; i++) {
        const size_t n = n0 + ty * 8 + i;
        #pragma unroll
        for (int jq = 0; jq < 2; jq++) {
            const int v = v0 + tx * 8 + jq * 4;
            if (v < V_) {
                float4 o;
                o.x = acc[i][jq * 4 + 0] + bo[v + 0];
                o.y = acc[i][jq * 4 + 1] + bo[v + 1];
                o.z = acc[i][jq * 4 + 2] + bo[v + 2];
                o.w = acc[i][jq * 4 + 3] + bo[v + 3];
                *(float4*)(out + n * V_ + v) = o;
            }
        }
    }
}

// ---------------- launch ----------------------------------------------------
extern "C" void kernel_launch(void* const* d_in, const int* in_sizes, int n_in,
                              void* d_out, int out_size)
{
    const int*   seq   = (const int*)  d_in[0];
    const float* smask = (const float*)d_in[1];
    const float* topo  = (const float*)d_in[2];
    const float* W     = (const float*)d_in[3];
    const float* U     = (const float*)d_in[4];
    const float* b     = (const float*)d_in[5];
    const float* emb   = (const float*)d_in[6];
    const float* Wo    = (const float*)d_in[7];
    const float* bo    = (const float*)d_in[8];
    float* out = (float*)d_out;

    cudaFuncSetAttribute(xw_kernel,  cudaFuncAttributeMaxDynamicSharedMemorySize, XW_SMEM_BYTES);
    cudaFuncSetAttribute(rec_kernel, cudaFuncAttributeMaxDynamicSharedMemorySize, REC_SMEM_BYTES);
    cudaFuncSetAttribute(out_kernel, cudaFuncAttributeMaxDynamicSharedMemorySize, OUT_SMEM_BYTES);

    xw_kernel<<<dim3((T_ * N_) / 128, H4_ / 128), 256, XW_SMEM_BYTES>>>(seq, emb, W, b);
    rec_kernel<<<NBLK, 256, REC_SMEM_BYTES>>>(topo, smask, U);
    out_kernel<<<dim3((V_ + 127) / 128, (N_ + 127) / 128), 256, OUT_SMEM_BYTES>>>(Wo, bo, out);
}

// round 16
// speedup vs baseline: 3.6589x; 1.0082x over previous
#include <cuda_runtime.h>
#include <math.h>

#define T_  200
#define N_  256
#define H_  128
#define H4_ 512
#define V_  50000

#define NB   2            // batch elements per block
#define NBLK (N_ / NB)    // 128 persistent blocks
#define KC   44           // history steps cached in smem (2KB each)

// ---- packed fp32x2 FMA (Blackwell FFMA2): d = a*b + d, per-lane IEEE fp32 ----
__device__ __forceinline__ void ffma2(float2& d, const float2 a, const float2 b) {
    asm("fma.rn.f32x2 %0, %1, %2, %0;"
        : "+l"(*reinterpret_cast<unsigned long long*>(&d))
        : "l"(*reinterpret_cast<const unsigned long long*>(&a)),
          "l"(*reinterpret_cast<const unsigned long long*>(&b)));
}

// ---------------- scratch (device globals; no runtime allocation) ----------
__device__ float  g_xw[(size_t)T_ * N_ * H4_];             // [t][n][4H]  ~105 MB
__device__ float2 g_hist2[(size_t)NBLK * T_ * NB * H_];    // ~52 MB
__device__ float  g_hmean[N_ * H_];

// ============================================================================
// kernel 1: xw[t,n,:] = emb[seq[t,n]] @ W + b
// 128x128 tile, split-K (2 x 64), 8x8 micro-tile via FFMA2 (packed j-pairs)
// ============================================================================
#define XW_AS_LD 132
#define XW_SMEM_BYTES ((64 * XW_AS_LD + 64 * 128) * 4)

__global__ __launch_bounds__(256) void xw_kernel(
    const int* __restrict__ seq, const float* __restrict__ emb,
    const float* __restrict__ W, const float* __restrict__ b)
{
    extern __shared__ float dynsmem[];
    float* As = dynsmem;                   // [k<64][r<128]  K-major, padded
    float* Bs = dynsmem + 64 * XW_AS_LD;   // [k<64][j<128]

    const int r0  = blockIdx.x * 128;
    const int j0  = blockIdx.y * 128;
    const int tid = threadIdx.x;

    const int ar = tid >> 1;
    const int ah = tid & 1;
    const int bk = tid >> 2;
    const int bq = tid & 3;
    const int s  = seq[r0 + ar];

    const int tx = tid & 15;
    const int ty = tid >> 4;
    float2 acc[8][4] = {};     // [row][col-pair]

    #pragma unroll
    for (int ks = 0; ks < 2; ks++) {
        if (ks) __syncthreads();

        {
            const float4* src = (const float4*)(emb + (size_t)s * H_ + ks * 64 + ah * 32);
            #pragma unroll
            for (int i = 0; i < 8; i++) {
                float4 v = src[i];
                const int k = ah * 32 + i * 4;
                As[(k + 0) * XW_AS_LD + ar] = v.x;
                As[(k + 1) * XW_AS_LD + ar] = v.y;
                As[(k + 2) * XW_AS_LD + ar] = v.z;
                As[(k + 3) * XW_AS_LD + ar] = v.w;
            }
        }
        {
            const float4* src = (const float4*)(W + (size_t)(ks * 64 + bk) * H4_ + j0 + bq * 32);
            float4* dst = (float4*)(Bs + bk * 128 + bq * 32);
            #pragma unroll
            for (int i = 0; i < 8; i++) dst[i] = src[i];
        }
        __syncthreads();

        #pragma unroll 2
        for (int k = 0; k < 64; k++) {
            float4 a0 = *(const float4*)(As + k * XW_AS_LD + ty * 8);
            float4 a1 = *(const float4*)(As + k * XW_AS_LD + ty * 8 + 4);
            float4 b0 = *(const float4*)(Bs + k * 128 + tx * 8);
            float4 b1 = *(const float4*)(Bs + k * 128 + tx * 8 + 4);
            const float av[8] = {a0.x, a0.y, a0.z, a0.w, a1.x, a1.y, a1.z, a1.w};
            const float2 bv[4] = {make_float2(b0.x, b0.y), make_float2(b0.z, b0.w),
                                  make_float2(b1.x, b1.y), make_float2(b1.z, b1.w)};
            #pragma unroll
            for (int i = 0; i < 8; i++) {
                const float2 as = make_float2(av[i], av[i]);
                #pragma unroll
                for (int jp = 0; jp < 4; jp++) ffma2(acc[i][jp], as, bv[jp]);
            }
        }
    }

    #pragma unroll
    for (int i = 0; i < 8; i++) {
        const size_t r = r0 + ty * 8 + i;
        #pragma unroll
        for (int jq = 0; jq < 2; jq++) {
            const int j = j0 + tx * 8 + jq * 4;
            float4 o;
            o.x = acc[i][jq * 2 + 0].x + b[j + 0];
            o.y = acc[i][jq * 2 + 0].y + b[j + 1];
            o.z = acc[i][jq * 2 + 1].x + b[j + 2];
            o.w = acc[i][jq * 2 + 1].y + b[j + 3];
            *(float4*)(g_xw + r * H4_ + j) = o;
        }
    }
}

// ============================================================================
// kernel 2: persistent recurrence (pipelined, smem history cache, FFMA2)
// ============================================================================
#define SM_SU   (128 * 256)
#define SM_HS   (128 * NB)
#define SM_G    (NB * H4_)
#define SM_TB   (NB * T_)
#define SM_MASK (NB * T_)
#define SM_HIST (KC * NB * H_ * 2)
#define REC_SMEM_BYTES ((SM_SU + SM_HS + SM_G + 2 * SM_TB + SM_MASK + SM_HIST) * 4)

__global__ __launch_bounds__(256, 1) void rec_kernel(
    const float* __restrict__ topo, const float* __restrict__ smask,
    const float* __restrict__ U)
{
    extern __shared__ float sm[];
    float*  sU     = sm;                    // [k][j], j -> U col 256+j
    float*  s_hs   = sU + SM_SU;            // [k][NB]
    float*  s_g    = s_hs + SM_HS;          // [n'][512]
    float*  s_topo = s_g + SM_G;            // [2][n'][T_]
    float*  s_mask = s_topo + 2 * SM_TB;    // [n'][T_]
    float2* s_hist = (float2*)(s_mask + SM_MASK);   // [KC][n'][H] -> (h,c)

    const int b   = blockIdx.x;
    const int tid = threadIdx.x;
    const int n0  = b * NB;
    const int an  = tid >> 7;
    const int ak  = tid & 127;

    // ---- prologue ----
    float u[128];
    #pragma unroll
    for (int k = 0; k < 128; k++) u[k] = U[(size_t)k * H4_ + tid];
    for (int idx = tid; idx < 128 * 256; idx += 256) {
        const int k = idx >> 8, j = idx & 255;
        sU[idx] = U[(size_t)k * H4_ + 256 + j];
    }
    for (int idx = tid; idx < NB * T_; idx += 256) {
        const int nn = idx / T_, tt = idx % T_;
        s_mask[nn * T_ + tt] = smask[tt * N_ + n0 + nn];
    }
    s_hs[tid] = 0.f;
    #pragma unroll
    for (int nn = 0; nn < NB; nn++) {
        const float* trow = topo + ((size_t)1 * N_ + n0 + nn) * T_;
        for (int i = tid; i < 2; i += 256) s_topo[1 * SM_TB + nn * T_ + i] = trow[i];
    }

    float2* hist = g_hist2 + (size_t)b * T_ * NB * H_;
    const int HS = NB * H_;

    float cs_cur = 0.f;
    float hmean_acc = 0.f, len_acc = 0.f;
    __syncthreads();                       // barrier alpha for iter 0

    for (int t = 0; t < T_; t++) {
        const bool more = (t + 1 < T_);

        // ---- prefetch this step's xw rows ----
        const float* xwp = g_xw + ((size_t)t * N_ + n0) * H4_;
        float x0 = xwp[tid];
        float x1 = xwp[H4_ + tid];
        float x2 = xwp[256 + tid];
        float x3 = xwp[H4_ + 256 + tid];

        // ---- stage topo row t+2 (early: latency hides under agg+gates) ----
        if (t + 2 < T_) {
            #pragma unroll
            for (int nn = 0; nn < NB; nn++) {
                const float* trow = topo + ((size_t)(t + 2) * N_ + n0 + nn) * T_;
                for (int i = tid; i < t + 2; i += 256)
                    s_topo[(t & 1) * SM_TB + nn * T_ + i] = trow[i];
            }
        }

        // ---- agg for step t+1 over t' in [0, t): packed (h,c) accumulators ----
        float hs_nx = 0.f, cs_nx = 0.f;
        if (more) {
            const float* tw = s_topo + ((t + 1) & 1) * SM_TB + an * T_;
            float2 hc0 = {0.f, 0.f}, hc1 = {0.f, 0.f};
            float2 hc2 = {0.f, 0.f}, hc3 = {0.f, 0.f};

            // --- smem-cached portion: t' in [0, min(t,KC)) ---
            const int tc = (t < KC) ? t : KC;
            const float2* sp = s_hist + an * H_ + ak;
            int tp = 0;
            for (; tp + 4 <= tc; tp += 4) {
                float2 v0 = sp[(tp + 0) * HS];
                float2 v1 = sp[(tp + 1) * HS];
                float2 v2 = sp[(tp + 2) * HS];
                float2 v3 = sp[(tp + 3) * HS];
                ffma2(hc0, make_float2(tw[tp + 0], tw[tp + 0]), v0);
                ffma2(hc1, make_float2(tw[tp + 1], tw[tp + 1]), v1);
                ffma2(hc2, make_float2(tw[tp + 2], tw[tp + 2]), v2);
                ffma2(hc3, make_float2(tw[tp + 3], tw[tp + 3]), v3);
            }
            for (; tp < tc; tp++) {
                ffma2(hc0, make_float2(tw[tp], tw[tp]), sp[tp * HS]);
            }

            // --- global portion: t' in [KC, t), MLP=16 batches ---
            const float2* hp = hist + an * H_ + ak;
            for (; tp + 16 <= t; tp += 16) {
                float2 v[16];
                #pragma unroll
                for (int i = 0; i < 16; i++) v[i] = hp[(size_t)(tp + i) * HS];
                #pragma unroll
                for (int i = 0; i < 16; i++) {
                    const float2 w2 = make_float2(tw[tp + i], tw[tp + i]);
                    switch (i & 3) {
                        case 0: ffma2(hc0, w2, v[i]); break;
                        case 1: ffma2(hc1, w2, v[i]); break;
                        case 2: ffma2(hc2, w2, v[i]); break;
                        default: ffma2(hc3, w2, v[i]); break;
                    }
                }
            }
            for (; tp < t; tp++) {
                ffma2(hc0, make_float2(tw[tp], tw[tp]), hp[(size_t)tp * HS]);
            }
            hs_nx = (hc0.x + hc1.x) + (hc2.x + hc3.x);
            cs_nx = (hc0.y + hc1.y) + (hc2.y + hc3.y);
        }

        // ---- gates GEMM for step t (FFMA2: 2 packed FMA per k) ----
        {
            float2 A01 = make_float2(x0, x1);   // (n0,n1) for col tid
            float2 A23 = make_float2(x2, x3);   // (n0,n1) for col 256+tid
            #pragma unroll
            for (int k = 0; k < 128; k++) {
                const float2 hv = *(const float2*)(s_hs + k * NB);  // (hs_n0, hs_n1)
                const float  ub = sU[k * 256 + tid];
                ffma2(A01, hv, make_float2(u[k], u[k]));
                ffma2(A23, hv, make_float2(ub, ub));
            }
            s_g[0 * H4_ + tid]       = A01.x;
            s_g[1 * H4_ + tid]       = A01.y;
            s_g[0 * H4_ + 256 + tid] = A23.x;
            s_g[1 * H4_ + 256 + tid] = A23.y;
        }
        __syncthreads();   // barrier beta: s_g ready; s_hs reads complete

        // ---- region 2: cell for t, last agg term from registers ----
        {
            const float ai = s_g[an * H4_ + ak];
            const float af = s_g[an * H4_ + 128 + ak];
            const float ao = s_g[an * H4_ + 256 + ak];
            const float ag = s_g[an * H4_ + 384 + ak];
            const float i_ = 1.f / (1.f + expf(-ai));
            const float f_ = 1.f / (1.f + expf(-af));
            const float o_ = 1.f / (1.f + expf(-ao));
            const float gv = tanhf(ag);
            const float m  = s_mask[an * T_ + t];

            const float c  = m * (f_ * cs_cur + i_ * gv);
            const float hv = m * (o_ * tanhf(c));

            if (t < KC) s_hist[t * HS + an * H_ + ak] = make_float2(hv, c);
            else        hist [(size_t)t * HS + an * H_ + ak] = make_float2(hv, c);
            hmean_acc += m * hv;
            len_acc   += m;

            if (more) {
                const float w = s_topo[((t + 1) & 1) * SM_TB + an * T_ + t];
                hs_nx += w * hv;
                cs_nx += w * c;
                s_hs[ak * NB + an] = hs_nx;
            }
            cs_cur = cs_nx;
        }
        __syncthreads();   // barrier alpha: s_hs / s_topo / s_hist ready
    }

    g_hmean[(n0 + an) * H_ + ak] = hmean_acc / len_acc;
}

// ============================================================================
// kernel 3: out = hmean @ W_out + b_out  (split-K 2x64, FFMA2 micro-tile)
// ============================================================================
#define OUT_AS_LD 132
#define OUT_SMEM_BYTES ((64 * OUT_AS_LD + 64 * 128) * 4)

__global__ __launch_bounds__(256) void out_kernel(
    const float* __restrict__ Wo, const float* __restrict__ bo,
    float* __restrict__ out)
{
    extern __shared__ float dynsmem[];
    float* As = dynsmem;                    // [k<64][n<128]
    float* Bs = dynsmem + 64 * OUT_AS_LD;   // [k<64][v<128]

    const int v0  = blockIdx.x * 128;
    const int n0  = blockIdx.y * 128;
    const int tid = threadIdx.x;

    const int ar = tid >> 1;
    const int ah = tid & 1;
    const int bk = tid >> 2;
    const int bq = tid & 3;

    const int tx = tid & 15;
    const int ty = tid >> 4;
    float2 acc[8][4] = {};

    #pragma unroll
    for (int ks = 0; ks < 2; ks++) {
        if (ks) __syncthreads();

        {
            const float4* src = (const float4*)(g_hmean + (size_t)(n0 + ar) * H_ + ks * 64 + ah * 32);
            #pragma unroll
            for (int i = 0; i < 8; i++) {
                float4 v = src[i];
                const int k = ah * 32 + i * 4;
                As[(k + 0) * OUT_AS_LD + ar] = v.x;
                As[(k + 1) * OUT_AS_LD + ar] = v.y;
                As[(k + 2) * OUT_AS_LD + ar] = v.z;
                As[(k + 3) * OUT_AS_LD + ar] = v.w;
            }
        }
        {
            #pragma unroll
            for (int i = 0; i < 8; i++) {
                const int v = v0 + bq * 32 + i * 4;
                float4 val = make_float4(0.f, 0.f, 0.f, 0.f);
                if (v < V_) val = *(const float4*)(Wo + (size_t)(ks * 64 + bk) * V_ + v);
                *(float4*)(Bs + bk * 128 + bq * 32 + i * 4) = val;
            }
        }
        __syncthreads();

        #pragma unroll 2
        for (int k = 0; k < 64; k++) {
            float4 a0 = *(const float4*)(As + k * OUT_AS_LD + ty * 8);
            float4 a1 = *(const float4*)(As + k * OUT_AS_LD + ty * 8 + 4);
            float4 b0 = *(const float4*)(Bs + k * 128 + tx * 8);
            float4 b1 = *(const float4*)(Bs + k * 128 + tx * 8 + 4);
            const float av[8] = {a0.x, a0.y, a0.z, a0.w, a1.x, a1.y, a1.z, a1.w};
            const float2 bv[4] = {make_float2(b0.x, b0.y), make_float2(b0.z, b0.w),
                                  make_float2(b1.x, b1.y), make_float2(b1.z, b1.w)};
            #pragma unroll
            for (int i = 0; i < 8; i++) {
                const float2 as = make_float2(av[i], av[i]);
                #pragma unroll
                for (int jp = 0; jp < 4; jp++) ffma2(acc[i][jp], as, bv[jp]);
            }
        }
    }

    #pragma unroll
    for (int i = 0; i < 8; i++) {
        const size_t n = n0 + ty * 8 + i;
        #pragma unroll
        for (int jq = 0; jq < 2; jq++) {
            const int v = v0 + tx * 8 + jq * 4;
            if (v < V_) {
                float4 o;
                o.x = acc[i][jq * 2 + 0].x + bo[v + 0];
                o.y = acc[i][jq * 2 + 0].y + bo[v + 1];
                o.z = acc[i][jq * 2 + 1].x + bo[v + 2];
                o.w = acc[i][jq * 2 + 1].y + bo[v + 3];
                *(float4*)(out + n * V_ + v) = o;
            }
        }
    }
}

// ---------------- launch ----------------------------------------------------
extern "C" void kernel_launch(void* const* d_in, const int* in_sizes, int n_in,
                              void* d_out, int out_size)
{
    const int*   seq   = (const int*)  d_in[0];
    const float* smask = (const float*)d_in[1];
    const float* topo  = (const float*)d_in[2];
    const float* W     = (const float*)d_in[3];
    const float* U     = (const float*)d_in[4];
    const float* b     = (const float*)d_in[5];
    const float* emb   = (const float*)d_in[6];
    const float* Wo    = (const float*)d_in[7];
    const float* bo    = (const float*)d_in[8];
    float* out = (float*)d_out;

    cudaFuncSetAttribute(xw_kernel,  cudaFuncAttributeMaxDynamicSharedMemorySize, XW_SMEM_BYTES);
    cudaFuncSetAttribute(rec_kernel, cudaFuncAttributeMaxDynamicSharedMemorySize, REC_SMEM_BYTES);
    cudaFuncSetAttribute(out_kernel, cudaFuncAttributeMaxDynamicSharedMemorySize, OUT_SMEM_BYTES);

    xw_kernel<<<dim3((T_ * N_) / 128, H4_ / 128), 256, XW_SMEM_BYTES>>>(seq, emb, W, b);
    rec_kernel<<<NBLK, 256, REC_SMEM_BYTES>>>(topo, smask, U);
    out_kernel<<<dim3((V_ + 127) / 128, (N_ + 127) / 128), 256, OUT_SMEM_BYTES>>>(Wo, bo, out);
}